// round 13
// baseline (speedup 1.0000x reference)
#include <cuda_runtime.h>
#include <cuda_bf16.h>
#include <math.h>
#include <stdint.h>

#define B_ 4
#define N_ 4096
#define D_ 1024
#define E_ 8
#define M_ 512   // N/E tokens per expert

// ---------------- scratch (device globals; no allocation allowed) ----------------
__device__ float g_t[B_ * N_ * E_];         // log(clamp(gate logits)) [b][n][e]
__device__ float g_r[B_ * N_];              // sinkhorn row (token) offsets
__device__ float g_c[B_ * E_];              // sinkhorn col (expert) offsets
__device__ int   g_topk_idx[B_ * E_ * M_];  // sorted token indices per (b,e), descending gate
__device__ float g_topk_val[B_ * E_ * M_];  // matching gate values
__device__ int   g_winner[B_ * N_];         // per-token winning key m*E+e (last-wins), -1 if unrouted

// sinkhorn cross-block partials (exchanged within an 8-CTA cluster via L2)
__device__ float2 g_part[2][B_][8][E_];     // [parity][b][seg][e] = (max, sum)

__device__ __forceinline__ uint32_t smem_u32(const void* p) {
    uint32_t a;
    asm("{ .reg .u64 t; cvta.to.shared.u64 t, %1; cvt.u32.u64 %0, t; }" : "=r"(a) : "l"(p));
    return a;
}
__device__ __forceinline__ void cp16(uint32_t dst, const void* src) {
    asm volatile("cp.async.cg.shared.global [%0], [%1], 16;" :: "r"(dst), "l"(src));
}
__device__ __forceinline__ void ldsm4(uint32_t* r, uint32_t addr) {
    asm volatile("ldmatrix.sync.aligned.m8n8.x4.shared.b16 {%0,%1,%2,%3}, [%4];"
                 : "=r"(r[0]), "=r"(r[1]), "=r"(r[2]), "=r"(r[3]) : "r"(addr));
}
__device__ __forceinline__ void mma_tf32(float* d, const uint32_t* a, const uint32_t* b) {
    asm volatile(
        "mma.sync.aligned.m16n8k8.row.col.f32.tf32.tf32.f32 "
        "{%0,%1,%2,%3}, {%4,%5,%6,%7}, {%8,%9}, {%0,%1,%2,%3};"
        : "+f"(d[0]), "+f"(d[1]), "+f"(d[2]), "+f"(d[3])
        : "r"(a[0]), "r"(a[1]), "r"(a[2]), "r"(a[3]), "r"(b[0]), "r"(b[1]));
}

// ========== k1: gate logits (+log clamp) + winner init ==========
__global__ __launch_bounds__(256) void gate_fused_kernel(
    const float* __restrict__ x, const float* __restrict__ gw) {
    __shared__ float sw[E_ * D_];   // gate weights transposed [e][d]
    int tid = threadIdx.x;
    for (int i = tid; i < D_ * E_; i += 256) {
        int d = i / E_, e = i % E_;
        sw[e * D_ + d] = gw[i];
    }
    if (blockIdx.x < (B_ * N_) / 256)
        g_winner[blockIdx.x * 256 + tid] = -1;
    __syncthreads();

    int warp = tid >> 5, lane = tid & 31;
    int row = blockIdx.x * 8 + warp;
    const float* xr = x + (size_t)row * D_;
    float acc[E_];
#pragma unroll
    for (int e = 0; e < E_; e++) acc[e] = 0.f;
    for (int d = lane; d < D_; d += 32) {
        float xv = xr[d];
#pragma unroll
        for (int e = 0; e < E_; e++) acc[e] += xv * sw[e * D_ + d];
    }
#pragma unroll
    for (int e = 0; e < E_; e++) {
#pragma unroll
        for (int off = 16; off; off >>= 1)
            acc[e] += __shfl_xor_sync(0xFFFFFFFFu, acc[e], off);
    }
    if (lane == 0) {
#pragma unroll
        for (int e = 0; e < E_; e++)
            g_t[(size_t)row * E_ + e] = logf(fmaxf(acc[e], 1e-6f));
    }
}

// ========== k2: distributed Sinkhorn, 32 blocks = 4 clusters of 8 (one per batch) ==========
#define SEG_TOK 512
#define SP 520
__global__ __launch_bounds__(1024) __cluster_dims__(8, 1, 1) void sinkhorn_kernel() {
    __shared__ float st[E_ * SP];     // this segment's logits [e][tok]
    __shared__ float sr[SEG_TOK];
    __shared__ float s_pm[32], s_ps[32], s_c[E_];

    int blk = blockIdx.x;             // 0..31; cluster = blocks 8b..8b+7
    int b = blk >> 3, seg = blk & 7;
    int n0 = seg * SEG_TOK;
    int tid = threadIdx.x;

    const float* tb = g_t + ((size_t)b * N_ + n0) * E_;
    for (int i = tid; i < SEG_TOK * E_; i += 1024) {
        int n = i >> 3, e = i & 7;
        st[e * SP + n] = tb[i];
    }
    if (tid < SEG_TOK) sr[tid] = 0.f;
    __syncthreads();

    int warp = tid >> 5, lane = tid & 31;
    int e_w = warp & 7, sub = warp >> 3;   // 4 warps per expert, 128 tokens per warp

    for (int it = 0; it < 8; it++) {
        // ---- col partial over this block's 512 tokens ----
        const float* se = st + e_w * SP;
        int base = sub * 128 + lane;
        float m = -INFINITY;
#pragma unroll
        for (int k = 0; k < 4; k++) m = fmaxf(m, se[base + k * 32] - sr[base + k * 32]);
#pragma unroll
        for (int off = 16; off; off >>= 1)
            m = fmaxf(m, __shfl_xor_sync(0xFFFFFFFFu, m, off));
        float s = 0.f;
#pragma unroll
        for (int k = 0; k < 4; k++) s += __expf(se[base + k * 32] - sr[base + k * 32] - m);
#pragma unroll
        for (int off = 16; off; off >>= 1)
            s += __shfl_xor_sync(0xFFFFFFFFu, s, off);
        if (lane == 0) { s_pm[warp] = m; s_ps[warp] = s; }
        __syncthreads();
        if (tid < E_) {
            float mm = fmaxf(fmaxf(s_pm[tid], s_pm[8 + tid]), fmaxf(s_pm[16 + tid], s_pm[24 + tid]));
            float ss = 0.f;
#pragma unroll
            for (int q = 0; q < 4; q++) ss += s_ps[q * 8 + tid] * __expf(s_pm[q * 8 + tid] - mm);
            g_part[it & 1][b][seg][tid] = make_float2(mm, ss);
        }
        __threadfence();   // make g_part visible before cluster barrier
        // ---- cluster barrier (8 CTAs of this batch) ----
        asm volatile("barrier.cluster.arrive.aligned;" ::: "memory");
        asm volatile("barrier.cluster.wait.aligned;" ::: "memory");
        // ---- merge 8 segment partials (fixed order -> deterministic) ----
        if (tid < E_) {
            float mm = -INFINITY, ss = 0.f;
#pragma unroll
            for (int sg = 0; sg < 8; sg++) {
                float2 p = g_part[it & 1][b][sg][tid];
                float nm = fmaxf(mm, p.x);
                ss = ss * __expf(mm - nm) + p.y * __expf(p.x - nm);
                mm = nm;
            }
            s_c[tid] = mm + __logf(ss);
        }
        __syncthreads();
        // ---- row phase (local): sr[n] = LSE_e(st[e][n] - c_e) ----
        if (tid < SEG_TOK) {
            int n = tid;
            float v0 = st[0 * SP + n] - s_c[0], v1 = st[1 * SP + n] - s_c[1];
            float v2 = st[2 * SP + n] - s_c[2], v3 = st[3 * SP + n] - s_c[3];
            float v4 = st[4 * SP + n] - s_c[4], v5 = st[5 * SP + n] - s_c[5];
            float v6 = st[6 * SP + n] - s_c[6], v7 = st[7 * SP + n] - s_c[7];
            float mm = fmaxf(fmaxf(fmaxf(v0, v1), fmaxf(v2, v3)),
                             fmaxf(fmaxf(v4, v5), fmaxf(v6, v7)));
            float ss = __expf(v0 - mm) + __expf(v1 - mm) + __expf(v2 - mm) + __expf(v3 - mm)
                     + __expf(v4 - mm) + __expf(v5 - mm) + __expf(v6 - mm) + __expf(v7 - mm);
            sr[n] = mm + __logf(ss);
        }
        __syncthreads();
    }
    if (tid < SEG_TOK) g_r[b * N_ + n0 + tid] = sr[tid];
    if (seg == 0 && tid < E_) g_c[b * E_ + tid] = s_c[tid];
}

// ========== k3: top-512 sort per (b,e) + winner scatter ==========
__global__ __launch_bounds__(1024) void topk_winner_kernel() {
    __shared__ unsigned long long keys[N_];
    int b = blockIdx.x >> 3, e = blockIdx.x & 7;
    int tid = threadIdx.x;
    const float* tb = g_t + (size_t)b * N_ * E_ + e;
    const float* rb = g_r + (size_t)b * N_;
    float ce = g_c[b * E_ + e];

    for (int i = tid; i < N_; i += 1024) {
        float v = tb[(size_t)i * E_] - rb[i];
        unsigned int u = __float_as_uint(v);
        u = (u & 0x80000000u) ? ~u : (u | 0x80000000u);
        keys[i] = ((unsigned long long)u << 32) | (unsigned int)(N_ - 1 - i);
    }
    __syncthreads();
    for (int k = 2; k <= N_; k <<= 1) {
        for (int j = k >> 1; j > 0; j >>= 1) {
            for (int i = tid; i < N_; i += 1024) {
                int l = i ^ j;
                if (l > i) {
                    unsigned long long a = keys[i], c = keys[l];
                    bool desc = ((i & k) == 0);
                    if (desc ? (a < c) : (a > c)) { keys[i] = c; keys[l] = a; }
                }
            }
            __syncthreads();
        }
    }
    for (int m = tid; m < M_; m += 1024) {
        unsigned long long K = keys[m];
        int n = (N_ - 1) - (int)(unsigned int)(K & 0xFFFFFFFFull);
        int o = (b * E_ + e) * M_ + m;
        g_topk_idx[o] = n;
        g_topk_val[o] = expf(tb[(size_t)n * E_] - rb[n] - ce);
        atomicMax(&g_winner[b * N_ + n], m * E_ + e);
    }
}

// ========== k4: tf32 mma.sync gathered expert GEMM (PROFILED LAUNCH) ==========
// CTA tile 128(m) x 128(f); 8 warps in 2x4 of 64x32; BK=32.
// 2-stage pipeline + __launch_bounds__(256,3): 3 CTAs/SM (occ 37.5%), smem 215KB/SM.
// A gathered directly from x (fp32->tf32 HW truncation), B direct from experts.
#define ROWF 36
#define BF   136
#define A_TILE_F (128 * ROWF * 4)        // 18432 B
#define B_TILE_F (32 * BF * 4)           // 17408 B
#define STAGE_F (A_TILE_F + B_TILE_F)    // 35840 B

__device__ __forceinline__ void load_stage_t(
    uint32_t sbase, int buf, int k0, int tid,
    const float* __restrict__ xb, const float* __restrict__ wb, const int* s_n)
{
    uint32_t sb = sbase + (uint32_t)buf * STAGE_F;
#pragma unroll
    for (int i = tid; i < 2048; i += 256) {
        uint32_t dst;
        const float* src;
        if (i < 1024) {                       // A: 128 rows x 8 cp16 (gathered x rows)
            int r = i >> 3, cc = i & 7;
            dst = sb + (uint32_t)r * (ROWF * 4) + (uint32_t)cc * 16;
            src = xb + (size_t)s_n[r] * D_ + k0 + cc * 4;
        } else {                              // B: 32 k-rows x 32 cp16 (direct experts)
            int j = i - 1024;
            int r = j >> 5, cc = j & 31;
            dst = sb + A_TILE_F + (uint32_t)r * (BF * 4) + (uint32_t)cc * 16;
            src = wb + (size_t)(k0 + r) * D_ + cc * 4;
        }
        cp16(dst, src);
    }
}

__global__ __launch_bounds__(256, 3) void expert_gemm_mma(
    const float* __restrict__ x, const float* __restrict__ experts, float* __restrict__ out) {
    extern __shared__ unsigned char dynsmem[];
    __shared__ int   s_n[128];
    __shared__ float s_v[128];
    __shared__ int   s_w[128];

    int bz = blockIdx.z;  int b = bz >> 3;  int e = bz & 7;
    int m0 = blockIdx.x * 128, f0 = blockIdx.y * 128;
    int tid = threadIdx.x, wid = tid >> 5, lane = tid & 31;
    int wm = wid & 1, wn = wid >> 1;   // warp tile: rows wm*64.., cols wn*32..

    uint32_t sbase = smem_u32(dynsmem);
    const uint32_t* smw = (const uint32_t*)dynsmem;

    if (tid < 128) {
        int o = bz * M_ + m0 + tid;
        int n = g_topk_idx[o];
        s_n[tid] = n;
        s_v[tid] = g_topk_val[o];
        s_w[tid] = (g_winner[b * N_ + n] == (m0 + tid) * E_ + e) ? 1 : 0;
    }
    __syncthreads();

    const float* xb = x + (size_t)b * N_ * D_;
    const float* wb = experts + (size_t)e * D_ * D_ + f0;

    float d[4][4][4];
#pragma unroll
    for (int i = 0; i < 4; i++)
#pragma unroll
        for (int j = 0; j < 4; j++)
#pragma unroll
            for (int q = 0; q < 4; q++) d[i][j][q] = 0.f;

    load_stage_t(sbase, 0, 0, tid, xb, wb, s_n);
    asm volatile("cp.async.commit_group;" ::: "memory");
    load_stage_t(sbase, 1, 32, tid, xb, wb, s_n);
    asm volatile("cp.async.commit_group;" ::: "memory");

    int qa = lane >> 2, ma = lane & 3;
    int arow = lane & 15;                 // ldmatrix row-within-16 for this lane
    int acol = (lane >> 4) << 2;          // 0 or 4 (tf32 col group)

#pragma unroll 1
    for (int c = 0; c < 32; c++) {
        if (c < 31) asm volatile("cp.async.wait_group 1;" ::: "memory");
        else        asm volatile("cp.async.wait_group 0;" ::: "memory");
        __syncthreads();

        int buf = c & 1;
        uint32_t abase = sbase + (uint32_t)buf * STAGE_F;
        const uint32_t* sbB = smw + (size_t)buf * (STAGE_F / 4) + A_TILE_F / 4;
#pragma unroll
        for (int kk = 0; kk < 32; kk += 8) {
            uint32_t afr[4][4], bfr[4][2];
#pragma unroll
            for (int mt = 0; mt < 4; mt++) {
                uint32_t ad = abase + (uint32_t)(wm * 64 + mt * 16 + arow) * (ROWF * 4)
                                    + (uint32_t)(kk + acol) * 4;
                ldsm4(afr[mt], ad);
            }
#pragma unroll
            for (int nt = 0; nt < 4; nt++) {
                int fc = wn * 32 + nt * 8 + qa;
                bfr[nt][0] = sbB[(kk + ma) * BF + fc];
                bfr[nt][1] = sbB[(kk + ma + 4) * BF + fc];
            }
#pragma unroll
            for (int mt = 0; mt < 4; mt++)
#pragma unroll
                for (int nt = 0; nt < 4; nt++) mma_tf32(d[mt][nt], afr[mt], bfr[nt]);
        }
        __syncthreads();
        if (c < 30) {
            load_stage_t(sbase, buf, (c + 2) * 32, tid, xb, wb, s_n);
            asm volatile("cp.async.commit_group;" ::: "memory");
        }
    }

    // epilogue: scale by gate value, winner-gated scatter
#pragma unroll
    for (int mt = 0; mt < 4; mt++) {
        int rbase = wm * 64 + mt * 16 + qa;
#pragma unroll
        for (int half = 0; half < 2; half++) {
            int r = rbase + half * 8;
            if (s_w[r]) {
                float sv = s_v[r];
                float* orow = out + ((size_t)b * N_ + s_n[r]) * D_ + f0 + wn * 32 + ma * 2;
#pragma unroll
                for (int nt = 0; nt < 4; nt++) {
                    float2 v;
                    v.x = d[mt][nt][half * 2 + 0] * sv;
                    v.y = d[mt][nt][half * 2 + 1] * sv;
                    *(float2*)(orow + nt * 8) = v;
                }
            }
        }
    }
}

// ========== k5: zero only unrouted rows ==========
__global__ void zero_unrouted_kernel(float4* __restrict__ out) {
    int row = blockIdx.x;
    if (g_winner[row] >= 0) return;
    out[(size_t)row * (D_ / 4) + threadIdx.x] = make_float4(0.f, 0.f, 0.f, 0.f);
}

// ---------------- launch ----------------
extern "C" void kernel_launch(void* const* d_in, const int* in_sizes, int n_in,
                              void* d_out, int out_size) {
    const float* x       = (const float*)d_in[0];
    const float* gw      = (const float*)d_in[1];
    const float* experts = (const float*)d_in[2];
    float* out = (float*)d_out;

    cudaFuncSetAttribute(expert_gemm_mma, cudaFuncAttributeMaxDynamicSharedMemorySize,
                         2 * STAGE_F);

    gate_fused_kernel<<<(B_ * N_) / 8, 256>>>(x, gw);
    sinkhorn_kernel<<<B_ * 8, 1024>>>();
    topk_winner_kernel<<<B_ * E_, 1024>>>();
    expert_gemm_mma<<<dim3(M_ / 128, D_ / 128, B_ * E_), 256, 2 * STAGE_F>>>(x, experts, out);
    zero_unrouted_kernel<<<B_ * N_, 256>>>((float4*)out);
}

// round 14
// speedup vs baseline: 1.2829x; 1.2829x over previous
#include <cuda_runtime.h>
#include <cuda_bf16.h>
#include <math.h>
#include <stdint.h>

#define B_ 4
#define N_ 4096
#define D_ 1024
#define E_ 8
#define M_ 512   // N/E tokens per expert

// ---------------- scratch (device globals; no allocation allowed) ----------------
__device__ float g_t[B_ * N_ * E_];         // log(clamp(gate logits)) [b][n][e]
__device__ float g_r[B_ * N_];              // sinkhorn row (token) offsets
__device__ float g_c[B_ * E_];              // sinkhorn col (expert) offsets
__device__ int   g_topk_idx[B_ * E_ * M_];  // sorted token indices per (b,e), descending gate
__device__ float g_topk_val[B_ * E_ * M_];  // matching gate values
__device__ int   g_winner[B_ * N_];         // per-token winning key m*E+e (last-wins), -1 if unrouted

// sinkhorn cross-block partials (exchanged within an 8-CTA cluster via L2)
__device__ float2 g_part[2][B_][8][E_];     // [parity][b][seg][e] = (max, sum)

__device__ __forceinline__ uint32_t smem_u32(const void* p) {
    uint32_t a;
    asm("{ .reg .u64 t; cvta.to.shared.u64 t, %1; cvt.u32.u64 %0, t; }" : "=r"(a) : "l"(p));
    return a;
}
__device__ __forceinline__ void cp16(uint32_t dst, const void* src) {
    asm volatile("cp.async.cg.shared.global [%0], [%1], 16;" :: "r"(dst), "l"(src));
}
__device__ __forceinline__ void ldsm4(uint32_t* r, uint32_t addr) {
    asm volatile("ldmatrix.sync.aligned.m8n8.x4.shared.b16 {%0,%1,%2,%3}, [%4];"
                 : "=r"(r[0]), "=r"(r[1]), "=r"(r[2]), "=r"(r[3]) : "r"(addr));
}
__device__ __forceinline__ void mma_tf32(float* d, const uint32_t* a, const uint32_t* b) {
    asm volatile(
        "mma.sync.aligned.m16n8k8.row.col.f32.tf32.tf32.f32 "
        "{%0,%1,%2,%3}, {%4,%5,%6,%7}, {%8,%9}, {%0,%1,%2,%3};"
        : "+f"(d[0]), "+f"(d[1]), "+f"(d[2]), "+f"(d[3])
        : "r"(a[0]), "r"(a[1]), "r"(a[2]), "r"(a[3]), "r"(b[0]), "r"(b[1]));
}

// ========== k1: gate logits (+log clamp) + winner init ==========
__global__ __launch_bounds__(256) void gate_fused_kernel(
    const float* __restrict__ x, const float* __restrict__ gw) {
    __shared__ float sw[E_ * D_];   // gate weights transposed [e][d]
    int tid = threadIdx.x;
    for (int i = tid; i < D_ * E_; i += 256) {
        int d = i / E_, e = i % E_;
        sw[e * D_ + d] = gw[i];
    }
    if (blockIdx.x < (B_ * N_) / 256)
        g_winner[blockIdx.x * 256 + tid] = -1;
    __syncthreads();

    int warp = tid >> 5, lane = tid & 31;
    int row = blockIdx.x * 8 + warp;
    const float* xr = x + (size_t)row * D_;
    float acc[E_];
#pragma unroll
    for (int e = 0; e < E_; e++) acc[e] = 0.f;
    for (int d = lane; d < D_; d += 32) {
        float xv = xr[d];
#pragma unroll
        for (int e = 0; e < E_; e++) acc[e] += xv * sw[e * D_ + d];
    }
#pragma unroll
    for (int e = 0; e < E_; e++) {
#pragma unroll
        for (int off = 16; off; off >>= 1)
            acc[e] += __shfl_xor_sync(0xFFFFFFFFu, acc[e], off);
    }
    if (lane == 0) {
#pragma unroll
        for (int e = 0; e < E_; e++)
            g_t[(size_t)row * E_ + e] = logf(fmaxf(acc[e], 1e-6f));
    }
}

// ========== k2: distributed Sinkhorn, 32 blocks = 4 clusters of 8 (one per batch) ==========
#define SEG_TOK 512
#define SP 520
__global__ __launch_bounds__(1024) __cluster_dims__(8, 1, 1) void sinkhorn_kernel() {
    __shared__ float st[E_ * SP];     // this segment's logits [e][tok]
    __shared__ float sr[SEG_TOK];
    __shared__ float s_pm[32], s_ps[32], s_c[E_];

    int blk = blockIdx.x;             // 0..31; cluster = blocks 8b..8b+7
    int b = blk >> 3, seg = blk & 7;
    int n0 = seg * SEG_TOK;
    int tid = threadIdx.x;

    const float* tb = g_t + ((size_t)b * N_ + n0) * E_;
    for (int i = tid; i < SEG_TOK * E_; i += 1024) {
        int n = i >> 3, e = i & 7;
        st[e * SP + n] = tb[i];
    }
    if (tid < SEG_TOK) sr[tid] = 0.f;
    __syncthreads();

    int warp = tid >> 5, lane = tid & 31;
    int e_w = warp & 7, sub = warp >> 3;   // 4 warps per expert, 128 tokens per warp

    for (int it = 0; it < 8; it++) {
        // ---- col partial over this block's 512 tokens ----
        const float* se = st + e_w * SP;
        int base = sub * 128 + lane;
        float m = -INFINITY;
#pragma unroll
        for (int k = 0; k < 4; k++) m = fmaxf(m, se[base + k * 32] - sr[base + k * 32]);
#pragma unroll
        for (int off = 16; off; off >>= 1)
            m = fmaxf(m, __shfl_xor_sync(0xFFFFFFFFu, m, off));
        float s = 0.f;
#pragma unroll
        for (int k = 0; k < 4; k++) s += __expf(se[base + k * 32] - sr[base + k * 32] - m);
#pragma unroll
        for (int off = 16; off; off >>= 1)
            s += __shfl_xor_sync(0xFFFFFFFFu, s, off);
        if (lane == 0) { s_pm[warp] = m; s_ps[warp] = s; }
        __syncthreads();
        if (tid < E_) {
            float mm = fmaxf(fmaxf(s_pm[tid], s_pm[8 + tid]), fmaxf(s_pm[16 + tid], s_pm[24 + tid]));
            float ss = 0.f;
#pragma unroll
            for (int q = 0; q < 4; q++) ss += s_ps[q * 8 + tid] * __expf(s_pm[q * 8 + tid] - mm);
            g_part[it & 1][b][seg][tid] = make_float2(mm, ss);
        }
        __threadfence();   // make g_part visible before cluster barrier
        // ---- cluster barrier (8 CTAs of this batch) ----
        asm volatile("barrier.cluster.arrive.aligned;" ::: "memory");
        asm volatile("barrier.cluster.wait.aligned;" ::: "memory");
        // ---- merge 8 segment partials (fixed order -> deterministic) ----
        if (tid < E_) {
            float mm = -INFINITY, ss = 0.f;
#pragma unroll
            for (int sg = 0; sg < 8; sg++) {
                float2 p = g_part[it & 1][b][sg][tid];
                float nm = fmaxf(mm, p.x);
                ss = ss * __expf(mm - nm) + p.y * __expf(p.x - nm);
                mm = nm;
            }
            s_c[tid] = mm + __logf(ss);
        }
        __syncthreads();
        // ---- row phase (local): sr[n] = LSE_e(st[e][n] - c_e) ----
        if (tid < SEG_TOK) {
            int n = tid;
            float v0 = st[0 * SP + n] - s_c[0], v1 = st[1 * SP + n] - s_c[1];
            float v2 = st[2 * SP + n] - s_c[2], v3 = st[3 * SP + n] - s_c[3];
            float v4 = st[4 * SP + n] - s_c[4], v5 = st[5 * SP + n] - s_c[5];
            float v6 = st[6 * SP + n] - s_c[6], v7 = st[7 * SP + n] - s_c[7];
            float mm = fmaxf(fmaxf(fmaxf(v0, v1), fmaxf(v2, v3)),
                             fmaxf(fmaxf(v4, v5), fmaxf(v6, v7)));
            float ss = __expf(v0 - mm) + __expf(v1 - mm) + __expf(v2 - mm) + __expf(v3 - mm)
                     + __expf(v4 - mm) + __expf(v5 - mm) + __expf(v6 - mm) + __expf(v7 - mm);
            sr[n] = mm + __logf(ss);
        }
        __syncthreads();
    }
    if (tid < SEG_TOK) g_r[b * N_ + n0 + tid] = sr[tid];
    if (seg == 0 && tid < E_) g_c[b * E_ + tid] = s_c[tid];
}

// ========== k3: top-512 sort per (b,e) + winner scatter ==========
__global__ __launch_bounds__(1024) void topk_winner_kernel() {
    __shared__ unsigned long long keys[N_];
    int b = blockIdx.x >> 3, e = blockIdx.x & 7;
    int tid = threadIdx.x;
    const float* tb = g_t + (size_t)b * N_ * E_ + e;
    const float* rb = g_r + (size_t)b * N_;
    float ce = g_c[b * E_ + e];

    for (int i = tid; i < N_; i += 1024) {
        float v = tb[(size_t)i * E_] - rb[i];
        unsigned int u = __float_as_uint(v);
        u = (u & 0x80000000u) ? ~u : (u | 0x80000000u);
        keys[i] = ((unsigned long long)u << 32) | (unsigned int)(N_ - 1 - i);
    }
    __syncthreads();
    for (int k = 2; k <= N_; k <<= 1) {
        for (int j = k >> 1; j > 0; j >>= 1) {
            for (int i = tid; i < N_; i += 1024) {
                int l = i ^ j;
                if (l > i) {
                    unsigned long long a = keys[i], c = keys[l];
                    bool desc = ((i & k) == 0);
                    if (desc ? (a < c) : (a > c)) { keys[i] = c; keys[l] = a; }
                }
            }
            __syncthreads();
        }
    }
    for (int m = tid; m < M_; m += 1024) {
        unsigned long long K = keys[m];
        int n = (N_ - 1) - (int)(unsigned int)(K & 0xFFFFFFFFull);
        int o = (b * E_ + e) * M_ + m;
        g_topk_idx[o] = n;
        g_topk_val[o] = expf(tb[(size_t)n * E_] - rb[n] - ce);
        atomicMax(&g_winner[b * N_ + n], m * E_ + e);
    }
}

// ========== k4: persistent tf32 mma.sync gathered expert GEMM (PROFILED LAUNCH) ==========
// 296 persistent CTAs (2/SM x 148); each loops tiles t = bid + k*296 over 1024 tiles.
// Tile = 128(m) x 128(f); 8 warps in 2x4 of 64x32; BK=32; R12 single-sync 3-stage pipeline.
// A gathered directly from x (fp32->tf32 HW truncation), B direct from experts.
#define ROWF 36
#define BF   136
#define A_TILE_F (128 * ROWF * 4)        // 18432 B
#define B_TILE_F (32 * BF * 4)           // 17408 B
#define STAGE_F (A_TILE_F + B_TILE_F)    // 35840 B
#define NTILES 1024
#define NPERS  296

__device__ __forceinline__ void load_stage_t(
    uint32_t sbase, int buf, int k0, int tid,
    const float* __restrict__ xb, const float* __restrict__ wb, const int* s_n)
{
    uint32_t sb = sbase + (uint32_t)buf * STAGE_F;
#pragma unroll
    for (int i = tid; i < 2048; i += 256) {
        uint32_t dst;
        const float* src;
        if (i < 1024) {                       // A: 128 rows x 8 cp16 (gathered x rows)
            int r = i >> 3, cc = i & 7;
            dst = sb + (uint32_t)r * (ROWF * 4) + (uint32_t)cc * 16;
            src = xb + (size_t)s_n[r] * D_ + k0 + cc * 4;
        } else {                              // B: 32 k-rows x 32 cp16 (direct experts)
            int j = i - 1024;
            int r = j >> 5, cc = j & 31;
            dst = sb + A_TILE_F + (uint32_t)r * (BF * 4) + (uint32_t)cc * 16;
            src = wb + (size_t)(k0 + r) * D_ + cc * 4;
        }
        cp16(dst, src);
    }
}

__global__ __launch_bounds__(256) void expert_gemm_mma(
    const float* __restrict__ x, const float* __restrict__ experts, float* __restrict__ out) {
    extern __shared__ unsigned char dynsmem[];
    __shared__ int   s_n[128];
    __shared__ float s_v[128];
    __shared__ int   s_w[128];

    int tid = threadIdx.x, wid = tid >> 5, lane = tid & 31;
    int wm = wid & 1, wn = wid >> 1;      // warp tile: rows wm*64.., cols wn*32..
    int qa = lane >> 2, ma = lane & 3;
    int arow = lane & 15;                 // ldmatrix row-within-16 for this lane
    int acol = (lane >> 4) << 2;          // 0 or 4 (tf32 col group)

    uint32_t sbase = smem_u32(dynsmem);
    const uint32_t* smw = (const uint32_t*)dynsmem;

#pragma unroll 1
    for (int t = blockIdx.x; t < NTILES; t += NPERS) {
        // decode tile: t = mx + 4*(fy + 8*bz)  -> consecutive t share bz (L2 reuse)
        int mx = t & 3;
        int rest = t >> 2;
        int fy = rest & 7;
        int bz = rest >> 3;
        int b = bz >> 3, e = bz & 7;
        int m0 = mx * 128, f0 = fy * 128;

        __syncthreads();   // prior tile's epilogue reads of s_n/s_v/s_w done
        if (tid < 128) {
            int o = bz * M_ + m0 + tid;
            int n = g_topk_idx[o];
            s_n[tid] = n;
            s_v[tid] = g_topk_val[o];
            s_w[tid] = (g_winner[b * N_ + n] == (m0 + tid) * E_ + e) ? 1 : 0;
        }
        __syncthreads();

        const float* xb = x + (size_t)b * N_ * D_;
        const float* wb = experts + (size_t)e * D_ * D_ + f0;

        float d[4][4][4];
#pragma unroll
        for (int i = 0; i < 4; i++)
#pragma unroll
            for (int j = 0; j < 4; j++)
#pragma unroll
                for (int q = 0; q < 4; q++) d[i][j][q] = 0.f;

        load_stage_t(sbase, 0, 0, tid, xb, wb, s_n);
        asm volatile("cp.async.commit_group;" ::: "memory");
        load_stage_t(sbase, 1, 32, tid, xb, wb, s_n);
        asm volatile("cp.async.commit_group;" ::: "memory");

#pragma unroll 1
        for (int c = 0; c < 32; c++) {
            if (c < 31) asm volatile("cp.async.wait_group 1;" ::: "memory");
            else        asm volatile("cp.async.wait_group 0;" ::: "memory");
            __syncthreads();

            // issue next-next chunk load FIRST so cp.async overlaps this chunk's MMAs
            if (c < 30) {
                int nbuf = (c + 2) % 3;
                load_stage_t(sbase, nbuf, (c + 2) * 32, tid, xb, wb, s_n);
                asm volatile("cp.async.commit_group;" ::: "memory");
            }

            int buf = c % 3;
            uint32_t abase = sbase + (uint32_t)buf * STAGE_F;
            const uint32_t* sbB = smw + (size_t)buf * (STAGE_F / 4) + A_TILE_F / 4;
#pragma unroll
            for (int kk = 0; kk < 32; kk += 8) {
                uint32_t afr[4][4], bfr[4][2];
#pragma unroll
                for (int mt = 0; mt < 4; mt++) {
                    uint32_t ad = abase + (uint32_t)(wm * 64 + mt * 16 + arow) * (ROWF * 4)
                                        + (uint32_t)(kk + acol) * 4;
                    ldsm4(afr[mt], ad);
                }
#pragma unroll
                for (int nt = 0; nt < 4; nt++) {
                    int fc = wn * 32 + nt * 8 + qa;
                    bfr[nt][0] = sbB[(kk + ma) * BF + fc];
                    bfr[nt][1] = sbB[(kk + ma + 4) * BF + fc];
                }
#pragma unroll
                for (int mt = 0; mt < 4; mt++)
#pragma unroll
                    for (int nt = 0; nt < 4; nt++) mma_tf32(d[mt][nt], afr[mt], bfr[nt]);
            }
            // no trailing sync: next iter's load targets a different buffer
        }

        // epilogue: scale by gate value, winner-gated scatter
#pragma unroll
        for (int mt = 0; mt < 4; mt++) {
            int rbase = wm * 64 + mt * 16 + qa;
#pragma unroll
            for (int half = 0; half < 2; half++) {
                int r = rbase + half * 8;
                if (s_w[r]) {
                    float sv = s_v[r];
                    float* orow = out + ((size_t)b * N_ + s_n[r]) * D_ + f0 + wn * 32 + ma * 2;
#pragma unroll
                    for (int nt = 0; nt < 4; nt++) {
                        float2 v;
                        v.x = d[mt][nt][half * 2 + 0] * sv;
                        v.y = d[mt][nt][half * 2 + 1] * sv;
                        *(float2*)(orow + nt * 8) = v;
                    }
                }
            }
        }
    }
}

// ========== k5: zero only unrouted rows ==========
__global__ void zero_unrouted_kernel(float4* __restrict__ out) {
    int row = blockIdx.x;
    if (g_winner[row] >= 0) return;
    out[(size_t)row * (D_ / 4) + threadIdx.x] = make_float4(0.f, 0.f, 0.f, 0.f);
}

// ---------------- launch ----------------
extern "C" void kernel_launch(void* const* d_in, const int* in_sizes, int n_in,
                              void* d_out, int out_size) {
    const float* x       = (const float*)d_in[0];
    const float* gw      = (const float*)d_in[1];
    const float* experts = (const float*)d_in[2];
    float* out = (float*)d_out;

    cudaFuncSetAttribute(expert_gemm_mma, cudaFuncAttributeMaxDynamicSharedMemorySize,
                         3 * STAGE_F);

    gate_fused_kernel<<<(B_ * N_) / 8, 256>>>(x, gw);
    sinkhorn_kernel<<<B_ * 8, 1024>>>();
    topk_winner_kernel<<<B_ * E_, 1024>>>();
    expert_gemm_mma<<<NPERS, 256, 3 * STAGE_F>>>(x, experts, out);
    zero_unrouted_kernel<<<B_ * N_, 256>>>((float4*)out);
}

// round 15
// speedup vs baseline: 1.4545x; 1.1337x over previous
#include <cuda_runtime.h>
#include <cuda_bf16.h>
#include <math.h>
#include <stdint.h>

#define B_ 4
#define N_ 4096
#define D_ 1024
#define E_ 8
#define M_ 512   // N/E tokens per expert

// ---------------- scratch (device globals; no allocation allowed) ----------------
__device__ float g_t[B_ * N_ * E_];         // log(clamp(gate logits)) [b][n][e]
__device__ float g_r[B_ * N_];              // sinkhorn row (token) offsets
__device__ float g_c[B_ * E_];              // sinkhorn col (expert) offsets
__device__ int   g_topk_idx[B_ * E_ * M_];  // sorted token indices per (b,e), descending gate
__device__ float g_topk_val[B_ * E_ * M_];  // matching gate values
__device__ int   g_winner[B_ * N_];         // per-token winning key m*E+e (last-wins), -1 if unrouted

// sinkhorn cross-block partials (exchanged within an 8-CTA cluster via L2)
__device__ float2 g_part[2][B_][8][E_];     // [parity][b][seg][e] = (max, sum)

__device__ __forceinline__ uint32_t smem_u32(const void* p) {
    uint32_t a;
    asm("{ .reg .u64 t; cvta.to.shared.u64 t, %1; cvt.u32.u64 %0, t; }" : "=r"(a) : "l"(p));
    return a;
}
__device__ __forceinline__ void cp16(uint32_t dst, const void* src) {
    asm volatile("cp.async.cg.shared.global [%0], [%1], 16;" :: "r"(dst), "l"(src));
}
__device__ __forceinline__ void ldsm4(uint32_t* r, uint32_t addr) {
    asm volatile("ldmatrix.sync.aligned.m8n8.x4.shared.b16 {%0,%1,%2,%3}, [%4];"
                 : "=r"(r[0]), "=r"(r[1]), "=r"(r[2]), "=r"(r[3]) : "r"(addr));
}
__device__ __forceinline__ void mma_tf32(float* d, const uint32_t* a, const uint32_t* b) {
    asm volatile(
        "mma.sync.aligned.m16n8k8.row.col.f32.tf32.tf32.f32 "
        "{%0,%1,%2,%3}, {%4,%5,%6,%7}, {%8,%9}, {%0,%1,%2,%3};"
        : "+f"(d[0]), "+f"(d[1]), "+f"(d[2]), "+f"(d[3])
        : "r"(a[0]), "r"(a[1]), "r"(a[2]), "r"(a[3]), "r"(b[0]), "r"(b[1]));
}

// ========== k1: gate logits (+log clamp) + winner init ==========
__global__ __launch_bounds__(256) void gate_fused_kernel(
    const float* __restrict__ x, const float* __restrict__ gw) {
    __shared__ float sw[E_ * D_];   // gate weights transposed [e][d]
    int tid = threadIdx.x;
    for (int i = tid; i < D_ * E_; i += 256) {
        int d = i / E_, e = i % E_;
        sw[e * D_ + d] = gw[i];
    }
    if (blockIdx.x < (B_ * N_) / 256)
        g_winner[blockIdx.x * 256 + tid] = -1;
    __syncthreads();

    int warp = tid >> 5, lane = tid & 31;
    int row = blockIdx.x * 8 + warp;
    const float* xr = x + (size_t)row * D_;
    float acc[E_];
#pragma unroll
    for (int e = 0; e < E_; e++) acc[e] = 0.f;
    for (int d = lane; d < D_; d += 32) {
        float xv = xr[d];
#pragma unroll
        for (int e = 0; e < E_; e++) acc[e] += xv * sw[e * D_ + d];
    }
#pragma unroll
    for (int e = 0; e < E_; e++) {
#pragma unroll
        for (int off = 16; off; off >>= 1)
            acc[e] += __shfl_xor_sync(0xFFFFFFFFu, acc[e], off);
    }
    if (lane == 0) {
#pragma unroll
        for (int e = 0; e < E_; e++)
            g_t[(size_t)row * E_ + e] = logf(fmaxf(acc[e], 1e-6f));
    }
}

// ========== k2: distributed Sinkhorn, 32 blocks = 4 clusters of 8 (one per batch) ==========
#define SEG_TOK 512
#define SP 520
__global__ __launch_bounds__(1024) __cluster_dims__(8, 1, 1) void sinkhorn_kernel() {
    __shared__ float st[E_ * SP];     // this segment's logits [e][tok]
    __shared__ float sr[SEG_TOK];
    __shared__ float s_pm[32], s_ps[32], s_c[E_];

    int blk = blockIdx.x;             // 0..31; cluster = blocks 8b..8b+7
    int b = blk >> 3, seg = blk & 7;
    int n0 = seg * SEG_TOK;
    int tid = threadIdx.x;

    const float* tb = g_t + ((size_t)b * N_ + n0) * E_;
    for (int i = tid; i < SEG_TOK * E_; i += 1024) {
        int n = i >> 3, e = i & 7;
        st[e * SP + n] = tb[i];
    }
    if (tid < SEG_TOK) sr[tid] = 0.f;
    __syncthreads();

    int warp = tid >> 5, lane = tid & 31;
    int e_w = warp & 7, sub = warp >> 3;   // 4 warps per expert, 128 tokens per warp

    for (int it = 0; it < 8; it++) {
        // ---- col partial over this block's 512 tokens ----
        const float* se = st + e_w * SP;
        int base = sub * 128 + lane;
        float m = -INFINITY;
#pragma unroll
        for (int k = 0; k < 4; k++) m = fmaxf(m, se[base + k * 32] - sr[base + k * 32]);
#pragma unroll
        for (int off = 16; off; off >>= 1)
            m = fmaxf(m, __shfl_xor_sync(0xFFFFFFFFu, m, off));
        float s = 0.f;
#pragma unroll
        for (int k = 0; k < 4; k++) s += __expf(se[base + k * 32] - sr[base + k * 32] - m);
#pragma unroll
        for (int off = 16; off; off >>= 1)
            s += __shfl_xor_sync(0xFFFFFFFFu, s, off);
        if (lane == 0) { s_pm[warp] = m; s_ps[warp] = s; }
        __syncthreads();
        if (tid < E_) {
            float mm = fmaxf(fmaxf(s_pm[tid], s_pm[8 + tid]), fmaxf(s_pm[16 + tid], s_pm[24 + tid]));
            float ss = 0.f;
#pragma unroll
            for (int q = 0; q < 4; q++) ss += s_ps[q * 8 + tid] * __expf(s_pm[q * 8 + tid] - mm);
            g_part[it & 1][b][seg][tid] = make_float2(mm, ss);
        }
        __threadfence();   // make g_part visible before cluster barrier
        // ---- cluster barrier (8 CTAs of this batch) ----
        asm volatile("barrier.cluster.arrive.aligned;" ::: "memory");
        asm volatile("barrier.cluster.wait.aligned;" ::: "memory");
        // ---- merge 8 segment partials (fixed order -> deterministic) ----
        if (tid < E_) {
            float mm = -INFINITY, ss = 0.f;
#pragma unroll
            for (int sg = 0; sg < 8; sg++) {
                float2 p = g_part[it & 1][b][sg][tid];
                float nm = fmaxf(mm, p.x);
                ss = ss * __expf(mm - nm) + p.y * __expf(p.x - nm);
                mm = nm;
            }
            s_c[tid] = mm + __logf(ss);
        }
        __syncthreads();
        // ---- row phase (local): sr[n] = LSE_e(st[e][n] - c_e) ----
        if (tid < SEG_TOK) {
            int n = tid;
            float v0 = st[0 * SP + n] - s_c[0], v1 = st[1 * SP + n] - s_c[1];
            float v2 = st[2 * SP + n] - s_c[2], v3 = st[3 * SP + n] - s_c[3];
            float v4 = st[4 * SP + n] - s_c[4], v5 = st[5 * SP + n] - s_c[5];
            float v6 = st[6 * SP + n] - s_c[6], v7 = st[7 * SP + n] - s_c[7];
            float mm = fmaxf(fmaxf(fmaxf(v0, v1), fmaxf(v2, v3)),
                             fmaxf(fmaxf(v4, v5), fmaxf(v6, v7)));
            float ss = __expf(v0 - mm) + __expf(v1 - mm) + __expf(v2 - mm) + __expf(v3 - mm)
                     + __expf(v4 - mm) + __expf(v5 - mm) + __expf(v6 - mm) + __expf(v7 - mm);
            sr[n] = mm + __logf(ss);
        }
        __syncthreads();
    }
    if (tid < SEG_TOK) g_r[b * N_ + n0 + tid] = sr[tid];
    if (seg == 0 && tid < E_) g_c[b * E_ + tid] = s_c[tid];
}

// ========== k3: register/shuffle bitonic top-512 per (b,e) + winner scatter ==========
// Each thread owns elements 4t..4t+3 in registers. j>=128: smem exchange;
// 4<=j<=64: warp shuffle; j=1,2: in-register. Selection bit-identical to
// the smem bitonic (same keys, same desc/ilt rule).
__global__ __launch_bounds__(1024) void topk_winner_kernel() {
    __shared__ unsigned long long keys[N_];
    int b = blockIdx.x >> 3, e = blockIdx.x & 7;
    int tid = threadIdx.x;
    const float* tb = g_t + (size_t)b * N_ * E_ + e;
    const float* rb = g_r + (size_t)b * N_;
    float ce = g_c[b * E_ + e];

    unsigned long long kq[4];
#pragma unroll
    for (int q = 0; q < 4; q++) {
        int i = tid * 4 + q;
        float v = tb[(size_t)i * E_] - rb[i];
        unsigned int u = __float_as_uint(v);
        u = (u & 0x80000000u) ? ~u : (u | 0x80000000u);
        kq[q] = ((unsigned long long)u << 32) | (unsigned int)(N_ - 1 - i);
    }

#define CSWAP_PAIR(lo, hi, dsc) do {                                     \
    unsigned long long _a = kq[lo], _b = kq[hi];                         \
    unsigned long long _mx = _a > _b ? _a : _b;                          \
    unsigned long long _mn = _a > _b ? _b : _a;                          \
    kq[lo] = (dsc) ? _mx : _mn;                                         \
    kq[hi] = (dsc) ? _mn : _mx;                                         \
} while (0)

#pragma unroll 1
    for (int k = 2; k <= N_; k <<= 1) {
        // smem passes: j >= 128 (cross-warp)
#pragma unroll 1
        for (int j = k >> 1; j >= 128; j >>= 1) {
#pragma unroll
            for (int q = 0; q < 4; q++) keys[tid * 4 + q] = kq[q];
            __syncthreads();
#pragma unroll
            for (int q = 0; q < 4; q++) {
                int i = tid * 4 + q;
                unsigned long long p = keys[i ^ j];
                bool dsc = ((i & k) == 0);
                bool ilt = ((i & j) == 0);
                unsigned long long mx = kq[q] > p ? kq[q] : p;
                unsigned long long mn = kq[q] > p ? p : kq[q];
                kq[q] = (dsc == ilt) ? mx : mn;
            }
            __syncthreads();
        }
        // shuffle passes: 4 <= j <= 64 (within warp; partner lane = lane ^ (j>>2))
#pragma unroll 1
        for (int j = ((k >> 1) < 64 ? (k >> 1) : 64); j >= 4; j >>= 1) {
#pragma unroll
            for (int q = 0; q < 4; q++) {
                int i = tid * 4 + q;
                unsigned long long p = __shfl_xor_sync(0xFFFFFFFFu, kq[q], j >> 2);
                bool dsc = ((i & k) == 0);
                bool ilt = ((i & j) == 0);
                unsigned long long mx = kq[q] > p ? kq[q] : p;
                unsigned long long mn = kq[q] > p ? p : kq[q];
                kq[q] = (dsc == ilt) ? mx : mn;
            }
        }
        // j = 2 (in-register), only when k >= 4
        if (k >= 4) {
            bool d = (((tid * 4) & k) == 0);
            CSWAP_PAIR(0, 2, d);
            CSWAP_PAIR(1, 3, d);
        }
        // j = 1 (in-register)
        {
            bool d0 = (((tid * 4) & k) == 0);
            bool d1 = ((((tid * 4) + 2) & k) == 0);
            CSWAP_PAIR(0, 1, d0);
            CSWAP_PAIR(2, 3, d1);
        }
    }
#undef CSWAP_PAIR

    // threads 0..127 hold ranks 0..511 in registers
    if (tid < 128) {
#pragma unroll
        for (int q = 0; q < 4; q++) {
            int m = tid * 4 + q;
            unsigned long long K = kq[q];
            int n = (N_ - 1) - (int)(unsigned int)(K & 0xFFFFFFFFull);
            int o = (b * E_ + e) * M_ + m;
            g_topk_idx[o] = n;
            g_topk_val[o] = expf(tb[(size_t)n * E_] - rb[n] - ce);
            atomicMax(&g_winner[b * N_ + n], m * E_ + e);
        }
    }
}

// ========== k4: tf32 mma.sync gathered expert GEMM (PROFILED LAUNCH) ==========
// R12-exact: CTA tile 128x128; 8 warps 2x4 of 64x32; BK=32; single-sync 3-stage.
#define ROWF 36
#define BF   136
#define A_TILE_F (128 * ROWF * 4)        // 18432 B
#define B_TILE_F (32 * BF * 4)           // 17408 B
#define STAGE_F (A_TILE_F + B_TILE_F)    // 35840 B

__device__ __forceinline__ void load_stage_t(
    uint32_t sbase, int buf, int k0, int tid,
    const float* __restrict__ xb, const float* __restrict__ wb, const int* s_n)
{
    uint32_t sb = sbase + (uint32_t)buf * STAGE_F;
#pragma unroll
    for (int i = tid; i < 2048; i += 256) {
        uint32_t dst;
        const float* src;
        if (i < 1024) {                       // A: 128 rows x 8 cp16 (gathered x rows)
            int r = i >> 3, cc = i & 7;
            dst = sb + (uint32_t)r * (ROWF * 4) + (uint32_t)cc * 16;
            src = xb + (size_t)s_n[r] * D_ + k0 + cc * 4;
        } else {                              // B: 32 k-rows x 32 cp16 (direct experts)
            int j = i - 1024;
            int r = j >> 5, cc = j & 31;
            dst = sb + A_TILE_F + (uint32_t)r * (BF * 4) + (uint32_t)cc * 16;
            src = wb + (size_t)(k0 + r) * D_ + cc * 4;
        }
        cp16(dst, src);
    }
}

__global__ __launch_bounds__(256) void expert_gemm_mma(
    const float* __restrict__ x, const float* __restrict__ experts, float* __restrict__ out) {
    extern __shared__ unsigned char dynsmem[];
    __shared__ int   s_n[128];
    __shared__ float s_v[128];
    __shared__ int   s_w[128];

    int bz = blockIdx.z;  int b = bz >> 3;  int e = bz & 7;
    int m0 = blockIdx.x * 128, f0 = blockIdx.y * 128;
    int tid = threadIdx.x, wid = tid >> 5, lane = tid & 31;
    int wm = wid & 1, wn = wid >> 1;   // warp tile: rows wm*64.., cols wn*32..

    uint32_t sbase = smem_u32(dynsmem);
    const uint32_t* smw = (const uint32_t*)dynsmem;

    if (tid < 128) {
        int o = bz * M_ + m0 + tid;
        int n = g_topk_idx[o];
        s_n[tid] = n;
        s_v[tid] = g_topk_val[o];
        s_w[tid] = (g_winner[b * N_ + n] == (m0 + tid) * E_ + e) ? 1 : 0;
    }
    __syncthreads();

    const float* xb = x + (size_t)b * N_ * D_;
    const float* wb = experts + (size_t)e * D_ * D_ + f0;

    float d[4][4][4];
#pragma unroll
    for (int i = 0; i < 4; i++)
#pragma unroll
        for (int j = 0; j < 4; j++)
#pragma unroll
            for (int q = 0; q < 4; q++) d[i][j][q] = 0.f;

    load_stage_t(sbase, 0, 0, tid, xb, wb, s_n);
    asm volatile("cp.async.commit_group;" ::: "memory");
    load_stage_t(sbase, 1, 32, tid, xb, wb, s_n);
    asm volatile("cp.async.commit_group;" ::: "memory");

    int qa = lane >> 2, ma = lane & 3;
    int arow = lane & 15;                 // ldmatrix row-within-16 for this lane
    int acol = (lane >> 4) << 2;          // 0 or 4 (tf32 col group)

#pragma unroll 1
    for (int c = 0; c < 32; c++) {
        if (c < 31) asm volatile("cp.async.wait_group 1;" ::: "memory");
        else        asm volatile("cp.async.wait_group 0;" ::: "memory");
        __syncthreads();

        // issue next-next chunk load FIRST so cp.async overlaps this chunk's MMAs
        if (c < 30) {
            int nbuf = (c + 2) % 3;
            load_stage_t(sbase, nbuf, (c + 2) * 32, tid, xb, wb, s_n);
            asm volatile("cp.async.commit_group;" ::: "memory");
        }

        int buf = c % 3;
        uint32_t abase = sbase + (uint32_t)buf * STAGE_F;
        const uint32_t* sbB = smw + (size_t)buf * (STAGE_F / 4) + A_TILE_F / 4;
#pragma unroll
        for (int kk = 0; kk < 32; kk += 8) {
            uint32_t afr[4][4], bfr[4][2];
#pragma unroll
            for (int mt = 0; mt < 4; mt++) {
                uint32_t ad = abase + (uint32_t)(wm * 64 + mt * 16 + arow) * (ROWF * 4)
                                    + (uint32_t)(kk + acol) * 4;
                ldsm4(afr[mt], ad);
            }
#pragma unroll
            for (int nt = 0; nt < 4; nt++) {
                int fc = wn * 32 + nt * 8 + qa;
                bfr[nt][0] = sbB[(kk + ma) * BF + fc];
                bfr[nt][1] = sbB[(kk + ma + 4) * BF + fc];
            }
#pragma unroll
            for (int mt = 0; mt < 4; mt++)
#pragma unroll
                for (int nt = 0; nt < 4; nt++) mma_tf32(d[mt][nt], afr[mt], bfr[nt]);
        }
        // no trailing sync: next iter's load targets a different buffer
    }

    // epilogue: scale by gate value, winner-gated scatter
#pragma unroll
    for (int mt = 0; mt < 4; mt++) {
        int rbase = wm * 64 + mt * 16 + qa;
#pragma unroll
        for (int half = 0; half < 2; half++) {
            int r = rbase + half * 8;
            if (s_w[r]) {
                float sv = s_v[r];
                float* orow = out + ((size_t)b * N_ + s_n[r]) * D_ + f0 + wn * 32 + ma * 2;
#pragma unroll
                for (int nt = 0; nt < 4; nt++) {
                    float2 v;
                    v.x = d[mt][nt][half * 2 + 0] * sv;
                    v.y = d[mt][nt][half * 2 + 1] * sv;
                    *(float2*)(orow + nt * 8) = v;
                }
            }
        }
    }
}

// ========== k5: zero only unrouted rows ==========
__global__ void zero_unrouted_kernel(float4* __restrict__ out) {
    int row = blockIdx.x;
    if (g_winner[row] >= 0) return;
    out[(size_t)row * (D_ / 4) + threadIdx.x] = make_float4(0.f, 0.f, 0.f, 0.f);
}

// ---------------- launch ----------------
extern "C" void kernel_launch(void* const* d_in, const int* in_sizes, int n_in,
                              void* d_out, int out_size) {
    const float* x       = (const float*)d_in[0];
    const float* gw      = (const float*)d_in[1];
    const float* experts = (const float*)d_in[2];
    float* out = (float*)d_out;

    cudaFuncSetAttribute(expert_gemm_mma, cudaFuncAttributeMaxDynamicSharedMemorySize,
                         3 * STAGE_F);

    gate_fused_kernel<<<(B_ * N_) / 8, 256>>>(x, gw);
    sinkhorn_kernel<<<B_ * 8, 1024>>>();
    topk_winner_kernel<<<B_ * E_, 1024>>>();
    expert_gemm_mma<<<dim3(M_ / 128, D_ / 128, B_ * E_), 256, 3 * STAGE_F>>>(x, experts, out);
    zero_unrouted_kernel<<<B_ * N_, 256>>>((float4*)out);
}

// round 16
// speedup vs baseline: 1.5319x; 1.0532x over previous
#include <cuda_runtime.h>
#include <cuda_bf16.h>
#include <math.h>
#include <stdint.h>

#define B_ 4
#define N_ 4096
#define D_ 1024
#define E_ 8
#define M_ 512   // N/E tokens per expert

// ---------------- scratch (device globals; no allocation allowed) ----------------
__device__ float g_t[B_ * N_ * E_];         // log(clamp(gate logits)) [b][n][e]
__device__ float g_tt[B_ * E_ * N_];        // transposed copy [b][e][n] (written by k2)
__device__ float g_r[B_ * N_];              // sinkhorn row (token) offsets
__device__ float g_c[B_ * E_];              // sinkhorn col (expert) offsets
__device__ int   g_topk_idx[B_ * E_ * M_];  // sorted token indices per (b,e), descending gate
__device__ float g_topk_val[B_ * E_ * M_];  // matching gate values
__device__ int   g_winner[B_ * N_];         // per-token winning key m*E+e (last-wins), -1 if unrouted

// sinkhorn cross-block partials (exchanged within an 8-CTA cluster via L2)
__device__ float2 g_part[2][B_][8][E_];     // [parity][b][seg][e] = (max, sum)

__device__ __forceinline__ uint32_t smem_u32(const void* p) {
    uint32_t a;
    asm("{ .reg .u64 t; cvta.to.shared.u64 t, %1; cvt.u32.u64 %0, t; }" : "=r"(a) : "l"(p));
    return a;
}
__device__ __forceinline__ void cp16(uint32_t dst, const void* src) {
    asm volatile("cp.async.cg.shared.global [%0], [%1], 16;" :: "r"(dst), "l"(src));
}
__device__ __forceinline__ void ldsm4(uint32_t* r, uint32_t addr) {
    asm volatile("ldmatrix.sync.aligned.m8n8.x4.shared.b16 {%0,%1,%2,%3}, [%4];"
                 : "=r"(r[0]), "=r"(r[1]), "=r"(r[2]), "=r"(r[3]) : "r"(addr));
}
__device__ __forceinline__ void mma_tf32(float* d, const uint32_t* a, const uint32_t* b) {
    asm volatile(
        "mma.sync.aligned.m16n8k8.row.col.f32.tf32.tf32.f32 "
        "{%0,%1,%2,%3}, {%4,%5,%6,%7}, {%8,%9}, {%0,%1,%2,%3};"
        : "+f"(d[0]), "+f"(d[1]), "+f"(d[2]), "+f"(d[3])
        : "r"(a[0]), "r"(a[1]), "r"(a[2]), "r"(a[3]), "r"(b[0]), "r"(b[1]));
}

// ========== k1: gate logits (+log clamp) + winner init (vectorized) ==========
__global__ __launch_bounds__(256) void gate_fused_kernel(
    const float* __restrict__ x, const float* __restrict__ gw) {
    __shared__ float sw[E_ * D_];   // gate weights transposed [e][d]
    int tid = threadIdx.x;
    for (int i = tid; i < D_ * E_; i += 256) {
        int d = i / E_, e = i % E_;
        sw[e * D_ + d] = gw[i];
    }
    if (blockIdx.x < (B_ * N_) / 256)
        g_winner[blockIdx.x * 256 + tid] = -1;
    __syncthreads();

    int warp = tid >> 5, lane = tid & 31;
    int row = blockIdx.x * 8 + warp;
    const float4* xr4 = (const float4*)(x + (size_t)row * D_);
    float acc[E_];
#pragma unroll
    for (int e = 0; e < E_; e++) acc[e] = 0.f;
#pragma unroll
    for (int k = 0; k < 8; k++) {
        int i4 = lane + k * 32;          // float4 index
        float4 v = xr4[i4];
#pragma unroll
        for (int e = 0; e < E_; e++) {
            float4 w = *(const float4*)&sw[e * D_ + i4 * 4];
            acc[e] += v.x * w.x + v.y * w.y + v.z * w.z + v.w * w.w;
        }
    }
#pragma unroll
    for (int e = 0; e < E_; e++) {
#pragma unroll
        for (int off = 16; off; off >>= 1)
            acc[e] += __shfl_xor_sync(0xFFFFFFFFu, acc[e], off);
    }
    if (lane == 0) {
#pragma unroll
        for (int e = 0; e < E_; e++)
            g_t[(size_t)row * E_ + e] = logf(fmaxf(acc[e], 1e-6f));
    }
}

// ========== k2: distributed Sinkhorn, 32 blocks = 4 clusters of 8 (one per batch) ==========
#define SEG_TOK 512
#define SP 520
__global__ __launch_bounds__(1024) __cluster_dims__(8, 1, 1) void sinkhorn_kernel() {
    __shared__ float st[E_ * SP];     // this segment's logits [e][tok]
    __shared__ float sr[SEG_TOK];
    __shared__ float s_pm[32], s_ps[32], s_c[E_];

    int blk = blockIdx.x;             // 0..31; cluster = blocks 8b..8b+7
    int b = blk >> 3, seg = blk & 7;
    int n0 = seg * SEG_TOK;
    int tid = threadIdx.x;

    const float* tb = g_t + ((size_t)b * N_ + n0) * E_;
    for (int i = tid; i < SEG_TOK * E_; i += 1024) {
        int n = i >> 3, e = i & 7;
        st[e * SP + n] = tb[i];
    }
    if (tid < SEG_TOK) sr[tid] = 0.f;
    __syncthreads();

    // write transposed copy for k3 (coalesced over n); bit-identical values
    for (int i = tid; i < E_ * SEG_TOK; i += 1024) {
        int e = i >> 9, n = i & (SEG_TOK - 1);
        g_tt[((size_t)b * E_ + e) * N_ + n0 + n] = st[e * SP + n];
    }

    int warp = tid >> 5, lane = tid & 31;
    int e_w = warp & 7, sub = warp >> 3;   // 4 warps per expert, 128 tokens per warp

    for (int it = 0; it < 8; it++) {
        // ---- col partial over this block's 512 tokens ----
        const float* se = st + e_w * SP;
        int base = sub * 128 + lane;
        float m = -INFINITY;
#pragma unroll
        for (int k = 0; k < 4; k++) m = fmaxf(m, se[base + k * 32] - sr[base + k * 32]);
#pragma unroll
        for (int off = 16; off; off >>= 1)
            m = fmaxf(m, __shfl_xor_sync(0xFFFFFFFFu, m, off));
        float s = 0.f;
#pragma unroll
        for (int k = 0; k < 4; k++) s += __expf(se[base + k * 32] - sr[base + k * 32] - m);
#pragma unroll
        for (int off = 16; off; off >>= 1)
            s += __shfl_xor_sync(0xFFFFFFFFu, s, off);
        if (lane == 0) { s_pm[warp] = m; s_ps[warp] = s; }
        __syncthreads();
        if (tid < E_) {
            float mm = fmaxf(fmaxf(s_pm[tid], s_pm[8 + tid]), fmaxf(s_pm[16 + tid], s_pm[24 + tid]));
            float ss = 0.f;
#pragma unroll
            for (int q = 0; q < 4; q++) ss += s_ps[q * 8 + tid] * __expf(s_pm[q * 8 + tid] - mm);
            g_part[it & 1][b][seg][tid] = make_float2(mm, ss);
        }
        __threadfence();   // make g_part visible before cluster barrier
        // ---- cluster barrier (8 CTAs of this batch) ----
        asm volatile("barrier.cluster.arrive.aligned;" ::: "memory");
        asm volatile("barrier.cluster.wait.aligned;" ::: "memory");
        // ---- merge 8 segment partials (fixed order -> deterministic) ----
        if (tid < E_) {
            float mm = -INFINITY, ss = 0.f;
#pragma unroll
            for (int sg = 0; sg < 8; sg++) {
                float2 p = g_part[it & 1][b][sg][tid];
                float nm = fmaxf(mm, p.x);
                ss = ss * __expf(mm - nm) + p.y * __expf(p.x - nm);
                mm = nm;
            }
            s_c[tid] = mm + __logf(ss);
        }
        __syncthreads();
        // ---- row phase (local): sr[n] = LSE_e(st[e][n] - c_e) ----
        if (tid < SEG_TOK) {
            int n = tid;
            float v0 = st[0 * SP + n] - s_c[0], v1 = st[1 * SP + n] - s_c[1];
            float v2 = st[2 * SP + n] - s_c[2], v3 = st[3 * SP + n] - s_c[3];
            float v4 = st[4 * SP + n] - s_c[4], v5 = st[5 * SP + n] - s_c[5];
            float v6 = st[6 * SP + n] - s_c[6], v7 = st[7 * SP + n] - s_c[7];
            float mm = fmaxf(fmaxf(fmaxf(v0, v1), fmaxf(v2, v3)),
                             fmaxf(fmaxf(v4, v5), fmaxf(v6, v7)));
            float ss = __expf(v0 - mm) + __expf(v1 - mm) + __expf(v2 - mm) + __expf(v3 - mm)
                     + __expf(v4 - mm) + __expf(v5 - mm) + __expf(v6 - mm) + __expf(v7 - mm);
            sr[n] = mm + __logf(ss);
        }
        __syncthreads();
    }
    if (tid < SEG_TOK) g_r[b * N_ + n0 + tid] = sr[tid];
    if (seg == 0 && tid < E_) g_c[b * E_ + tid] = s_c[tid];
}

// ========== k3: register/shuffle bitonic top-512 per (b,e) + winner scatter ==========
__global__ __launch_bounds__(1024) void topk_winner_kernel() {
    __shared__ unsigned long long keys[N_];
    int b = blockIdx.x >> 3, e = blockIdx.x & 7;
    int tid = threadIdx.x;
    const float* tt = g_tt + ((size_t)b * E_ + e) * N_;   // contiguous column
    const float* rb = g_r + (size_t)b * N_;
    float ce = g_c[b * E_ + e];

    unsigned long long kq[4];
#pragma unroll
    for (int q = 0; q < 4; q++) {
        int i = tid * 4 + q;
        float v = tt[i] - rb[i];
        unsigned int u = __float_as_uint(v);
        u = (u & 0x80000000u) ? ~u : (u | 0x80000000u);
        kq[q] = ((unsigned long long)u << 32) | (unsigned int)(N_ - 1 - i);
    }

#define CSWAP_PAIR(lo, hi, dsc) do {                                     \
    unsigned long long _a = kq[lo], _b = kq[hi];                         \
    unsigned long long _mx = _a > _b ? _a : _b;                          \
    unsigned long long _mn = _a > _b ? _b : _a;                          \
    kq[lo] = (dsc) ? _mx : _mn;                                         \
    kq[hi] = (dsc) ? _mn : _mx;                                         \
} while (0)

#pragma unroll 1
    for (int k = 2; k <= N_; k <<= 1) {
        // smem passes: j >= 128 (cross-warp)
#pragma unroll 1
        for (int j = k >> 1; j >= 128; j >>= 1) {
#pragma unroll
            for (int q = 0; q < 4; q++) keys[tid * 4 + q] = kq[q];
            __syncthreads();
#pragma unroll
            for (int q = 0; q < 4; q++) {
                int i = tid * 4 + q;
                unsigned long long p = keys[i ^ j];
                bool dsc = ((i & k) == 0);
                bool ilt = ((i & j) == 0);
                unsigned long long mx = kq[q] > p ? kq[q] : p;
                unsigned long long mn = kq[q] > p ? p : kq[q];
                kq[q] = (dsc == ilt) ? mx : mn;
            }
            __syncthreads();
        }
        // shuffle passes: 4 <= j <= 64 (within warp)
#pragma unroll 1
        for (int j = ((k >> 1) < 64 ? (k >> 1) : 64); j >= 4; j >>= 1) {
#pragma unroll
            for (int q = 0; q < 4; q++) {
                int i = tid * 4 + q;
                unsigned long long p = __shfl_xor_sync(0xFFFFFFFFu, kq[q], j >> 2);
                bool dsc = ((i & k) == 0);
                bool ilt = ((i & j) == 0);
                unsigned long long mx = kq[q] > p ? kq[q] : p;
                unsigned long long mn = kq[q] > p ? p : kq[q];
                kq[q] = (dsc == ilt) ? mx : mn;
            }
        }
        if (k >= 4) {
            bool d = (((tid * 4) & k) == 0);
            CSWAP_PAIR(0, 2, d);
            CSWAP_PAIR(1, 3, d);
        }
        {
            bool d0 = (((tid * 4) & k) == 0);
            bool d1 = ((((tid * 4) + 2) & k) == 0);
            CSWAP_PAIR(0, 1, d0);
            CSWAP_PAIR(2, 3, d1);
        }
    }
#undef CSWAP_PAIR

    if (tid < 128) {
#pragma unroll
        for (int q = 0; q < 4; q++) {
            int m = tid * 4 + q;
            unsigned long long K = kq[q];
            int n = (N_ - 1) - (int)(unsigned int)(K & 0xFFFFFFFFull);
            int o = (b * E_ + e) * M_ + m;
            g_topk_idx[o] = n;
            g_topk_val[o] = expf(tt[n] - rb[n] - ce);
            atomicMax(&g_winner[b * N_ + n], m * E_ + e);
        }
    }
}

// ========== k4: tf32 mma.sync gathered expert GEMM + fused unrouted-zeroing ==========
// R12-exact GEMM; grid.z = 33: bz<32 GEMM tiles, bz==32 -> 32 zero-duty CTAs
// (dispatched last, fill the tail wave; rows disjoint from GEMM-written rows).
#define ROWF 36
#define BF   136
#define A_TILE_F (128 * ROWF * 4)        // 18432 B
#define B_TILE_F (32 * BF * 4)           // 17408 B
#define STAGE_F (A_TILE_F + B_TILE_F)    // 35840 B

__device__ __forceinline__ void load_stage_t(
    uint32_t sbase, int buf, int k0, int tid,
    const float* __restrict__ xb, const float* __restrict__ wb, const int* s_n)
{
    uint32_t sb = sbase + (uint32_t)buf * STAGE_F;
#pragma unroll
    for (int i = tid; i < 2048; i += 256) {
        uint32_t dst;
        const float* src;
        if (i < 1024) {                       // A: 128 rows x 8 cp16 (gathered x rows)
            int r = i >> 3, cc = i & 7;
            dst = sb + (uint32_t)r * (ROWF * 4) + (uint32_t)cc * 16;
            src = xb + (size_t)s_n[r] * D_ + k0 + cc * 4;
        } else {                              // B: 32 k-rows x 32 cp16 (direct experts)
            int j = i - 1024;
            int r = j >> 5, cc = j & 31;
            dst = sb + A_TILE_F + (uint32_t)r * (BF * 4) + (uint32_t)cc * 16;
            src = wb + (size_t)(k0 + r) * D_ + cc * 4;
        }
        cp16(dst, src);
    }
}

__global__ __launch_bounds__(256) void expert_gemm_mma(
    const float* __restrict__ x, const float* __restrict__ experts, float* __restrict__ out) {
    extern __shared__ unsigned char dynsmem[];
    __shared__ int   s_n[128];
    __shared__ float s_v[128];
    __shared__ int   s_w[128];

    int bz = blockIdx.z;
    int tid = threadIdx.x;

    if (bz == 32) {
        // zero-duty CTA: flat id 0..31, each covers 512 rows
        int fid = blockIdx.x + 4 * blockIdx.y;
        float4 z = make_float4(0.f, 0.f, 0.f, 0.f);
        for (int r = fid * 512; r < (fid + 1) * 512; r++) {
            if (g_winner[r] < 0) {
                float4* orow = (float4*)(out + (size_t)r * D_);
                orow[tid] = z;
            }
        }
        return;
    }

    int b = bz >> 3;  int e = bz & 7;
    int m0 = blockIdx.x * 128, f0 = blockIdx.y * 128;
    int wid = tid >> 5, lane = tid & 31;
    int wm = wid & 1, wn = wid >> 1;   // warp tile: rows wm*64.., cols wn*32..

    uint32_t sbase = smem_u32(dynsmem);
    const uint32_t* smw = (const uint32_t*)dynsmem;

    if (tid < 128) {
        int o = bz * M_ + m0 + tid;
        int n = g_topk_idx[o];
        s_n[tid] = n;
        s_v[tid] = g_topk_val[o];
        s_w[tid] = (g_winner[b * N_ + n] == (m0 + tid) * E_ + e) ? 1 : 0;
    }
    __syncthreads();

    const float* xb = x + (size_t)b * N_ * D_;
    const float* wb = experts + (size_t)e * D_ * D_ + f0;

    float d[4][4][4];
#pragma unroll
    for (int i = 0; i < 4; i++)
#pragma unroll
        for (int j = 0; j < 4; j++)
#pragma unroll
            for (int q = 0; q < 4; q++) d[i][j][q] = 0.f;

    load_stage_t(sbase, 0, 0, tid, xb, wb, s_n);
    asm volatile("cp.async.commit_group;" ::: "memory");
    load_stage_t(sbase, 1, 32, tid, xb, wb, s_n);
    asm volatile("cp.async.commit_group;" ::: "memory");

    int qa = lane >> 2, ma = lane & 3;
    int arow = lane & 15;                 // ldmatrix row-within-16 for this lane
    int acol = (lane >> 4) << 2;          // 0 or 4 (tf32 col group)

#pragma unroll 1
    for (int c = 0; c < 32; c++) {
        if (c < 31) asm volatile("cp.async.wait_group 1;" ::: "memory");
        else        asm volatile("cp.async.wait_group 0;" ::: "memory");
        __syncthreads();

        // issue next-next chunk load FIRST so cp.async overlaps this chunk's MMAs
        if (c < 30) {
            int nbuf = (c + 2) % 3;
            load_stage_t(sbase, nbuf, (c + 2) * 32, tid, xb, wb, s_n);
            asm volatile("cp.async.commit_group;" ::: "memory");
        }

        int buf = c % 3;
        uint32_t abase = sbase + (uint32_t)buf * STAGE_F;
        const uint32_t* sbB = smw + (size_t)buf * (STAGE_F / 4) + A_TILE_F / 4;
#pragma unroll
        for (int kk = 0; kk < 32; kk += 8) {
            uint32_t afr[4][4], bfr[4][2];
#pragma unroll
            for (int mt = 0; mt < 4; mt++) {
                uint32_t ad = abase + (uint32_t)(wm * 64 + mt * 16 + arow) * (ROWF * 4)
                                    + (uint32_t)(kk + acol) * 4;
                ldsm4(afr[mt], ad);
            }
#pragma unroll
            for (int nt = 0; nt < 4; nt++) {
                int fc = wn * 32 + nt * 8 + qa;
                bfr[nt][0] = sbB[(kk + ma) * BF + fc];
                bfr[nt][1] = sbB[(kk + ma + 4) * BF + fc];
            }
#pragma unroll
            for (int mt = 0; mt < 4; mt++)
#pragma unroll
                for (int nt = 0; nt < 4; nt++) mma_tf32(d[mt][nt], afr[mt], bfr[nt]);
        }
        // no trailing sync: next iter's load targets a different buffer
    }

    // epilogue: scale by gate value, winner-gated scatter
#pragma unroll
    for (int mt = 0; mt < 4; mt++) {
        int rbase = wm * 64 + mt * 16 + qa;
#pragma unroll
        for (int half = 0; half < 2; half++) {
            int r = rbase + half * 8;
            if (s_w[r]) {
                float sv = s_v[r];
                float* orow = out + ((size_t)b * N_ + s_n[r]) * D_ + f0 + wn * 32 + ma * 2;
#pragma unroll
                for (int nt = 0; nt < 4; nt++) {
                    float2 v;
                    v.x = d[mt][nt][half * 2 + 0] * sv;
                    v.y = d[mt][nt][half * 2 + 1] * sv;
                    *(float2*)(orow + nt * 8) = v;
                }
            }
        }
    }
}

// ---------------- launch ----------------
extern "C" void kernel_launch(void* const* d_in, const int* in_sizes, int n_in,
                              void* d_out, int out_size) {
    const float* x       = (const float*)d_in[0];
    const float* gw      = (const float*)d_in[1];
    const float* experts = (const float*)d_in[2];
    float* out = (float*)d_out;

    cudaFuncSetAttribute(expert_gemm_mma, cudaFuncAttributeMaxDynamicSharedMemorySize,
                         3 * STAGE_F);

    gate_fused_kernel<<<(B_ * N_) / 8, 256>>>(x, gw);
    sinkhorn_kernel<<<B_ * 8, 1024>>>();
    topk_winner_kernel<<<B_ * E_, 1024>>>();
    expert_gemm_mma<<<dim3(M_ / 128, D_ / 128, B_ * E_ + 1), 256, 3 * STAGE_F>>>(x, experts, out);
}